// round 4
// baseline (speedup 1.0000x reference)
#include <cuda_runtime.h>

// Batched 256-point complex DFT, out = FFT(x) / sqrt(256).
// Four-step: 256 = 16 x 16. 16 threads/frame, 16 frames per 256-thread block.
// Strided LDG.32/STG.32 (sector-coalesced). The 16x16 transpose goes through
// shared as packed float2, synced with __syncwarp (2 frames per warp).
// W16 twiddles are immediates. The W256^{t*k} step-2 twiddles are computed
// in registers from W256^t (row 1 of the input W matrix) via a shallow
// power tree with the 1/16 scale folded in -> no twiddle table, no LDS for
// twiddles, and no block-wide barrier at all.

#define NPT      256
#define FPB      16
#define BLOCK    256
#define ROWS     17                 // padded row stride, float2 units
#define FS2      (16 * ROWS)        // frame stride, float2 units (272)

__device__ __forceinline__ float2 cmul(float2 a, float2 b)
{
    return make_float2(a.x * b.x - a.y * b.y,
                       a.x * b.y + a.y * b.x);
}

__device__ __forceinline__ void dft4(
    float& r0, float& i0, float& r1, float& i1,
    float& r2, float& i2, float& r3, float& i3)
{
    float t0r = r0 + r2, t0i = i0 + i2;
    float t1r = r0 - r2, t1i = i0 - i2;
    float t2r = r1 + r3, t2i = i1 + i3;
    float t3r = r1 - r3, t3i = i1 - i3;
    r0 = t0r + t2r;  i0 = t0i + t2i;
    r2 = t0r - t2r;  i2 = t0i - t2i;
    r1 = t1r + t3i;  i1 = t1i - t3r;   // t1 - i*t3
    r3 = t1r - t3i;  i3 = t1i + t3r;   // t1 + i*t3
}

// In-register forward 16-pt DFT (two radix-4 stages, DIT).
// Output X[4*k1+k2] lives in slot (4*k2+k1); callers remap with rev4().
__device__ __forceinline__ void fft16(float* xr, float* xi)
{
    constexpr float WR[10] = {
        1.f,  0.92387953251128674f,  0.70710678118654752f,  0.38268343236508977f,
        0.f, -0.38268343236508977f, -0.70710678118654752f, -0.92387953251128674f,
       -1.f, -0.92387953251128674f };
    constexpr float WI[10] = {
        0.f, -0.38268343236508977f, -0.70710678118654752f, -0.92387953251128674f,
       -1.f, -0.92387953251128674f, -0.70710678118654752f, -0.38268343236508977f,
        0.f,  0.38268343236508977f };

#pragma unroll
    for (int n1 = 0; n1 < 4; n1++) {
        dft4(xr[n1],    xi[n1],
             xr[n1+4],  xi[n1+4],
             xr[n1+8],  xi[n1+8],
             xr[n1+12], xi[n1+12]);
    }
#pragma unroll
    for (int n1 = 1; n1 < 4; n1++) {
#pragma unroll
        for (int k2 = 1; k2 < 4; k2++) {
            int s = n1 + 4 * k2;
            int m = n1 * k2;               // 1..9
            float wr = WR[m], wi = WI[m];
            float ar = xr[s], ai = xi[s];
            xr[s] = ar * wr - ai * wi;
            xi[s] = ar * wi + ai * wr;
        }
    }
#pragma unroll
    for (int k2 = 0; k2 < 4; k2++) {
        dft4(xr[4*k2+0], xi[4*k2+0],
             xr[4*k2+1], xi[4*k2+1],
             xr[4*k2+2], xi[4*k2+2],
             xr[4*k2+3], xi[4*k2+3]);
    }
}

__device__ __forceinline__ int rev4(int k) { return ((k & 3) << 2) | (k >> 2); }

__global__ void __launch_bounds__(BLOCK, 6)
dft256_kernel(const float* __restrict__ xr, const float* __restrict__ xi,
              const float* __restrict__ Wr, const float* __restrict__ Wi,
              float* __restrict__ outR, float* __restrict__ outI)
{
    __shared__ float2 sh[FPB * FS2];     // transpose buffer (re,im packed)

    const int tid = threadIdx.x;
    const int f = tid >> 4;              // frame within block
    const int t = tid & 15;              // lane within frame (half-warp local)

    const size_t frame = (size_t)blockIdx.x * FPB + f;
    const float* xrp = xr + frame * NPT;
    const float* xip = xi + frame * NPT;

    // ---- step 1: strided coalesced loads, first fft16 (over n2) ----
    float ar[16], ai[16];
#pragma unroll
    for (int n2 = 0; n2 < 16; n2++) {
        ar[n2] = __ldcs(xrp + n2 * 16 + t);
        ai[n2] = __ldcs(xip + n2 * 16 + t);
    }
    fft16(ar, ai);

    // ---- step-2 twiddles in registers: W256^{t*k} / 16 via power tree ----
    // w1 = W256^t from row 1 of W; w^{4h+l} = Q[h] * L[l], Q pre-scaled.
    float2 w1 = make_float2(Wr[NPT + t], Wi[NPT + t]);
    float2 w2 = cmul(w1, w1);
    float2 w3 = cmul(w2, w1);
    float2 w4 = cmul(w2, w2);
    float2 w8 = cmul(w4, w4);
    float2 L[4] = { make_float2(1.f, 0.f), w1, w2, w3 };
    float2 Q[4];
    Q[0] = make_float2(0.0625f, 0.f);
    Q[1] = make_float2(0.0625f * w4.x, 0.0625f * w4.y);
    Q[2] = make_float2(0.0625f * w8.x, 0.0625f * w8.y);
    Q[3] = cmul(Q[2], w4);               // w12 / 16

    // ---- step 2: twiddle + transposed float2 STS ----
    float2* s = sh + f * FS2;
#pragma unroll
    for (int k = 0; k < 16; k++) {
        int sl = rev4(k);
        float2 wk = cmul(Q[k >> 2], L[k & 3]);
        float2 v  = make_float2(ar[sl], ai[sl]);
        s[k * ROWS + t] = cmul(v, wk);
    }
    __syncwarp();                        // transpose is intra-warp (2 frames/warp)

    // ---- step 3: row LDS.64, second fft16 (over n1) ----
    float br[16], bi[16];
#pragma unroll
    for (int n1 = 0; n1 < 16; n1++) {
        float2 v = s[t * ROWS + n1];
        br[n1] = v.x;  bi[n1] = v.y;
    }
    fft16(br, bi);

    // ---- step 4: strided coalesced streaming stores ----
    float* orp = outR + frame * NPT;
    float* oip = outI + frame * NPT;
#pragma unroll
    for (int k1 = 0; k1 < 16; k1++) {
        int sl = rev4(k1);
        __stcs(orp + k1 * 16 + t, br[sl]);
        __stcs(oip + k1 * 16 + t, bi[sl]);
    }
}

extern "C" void kernel_launch(void* const* d_in, const int* in_sizes, int n_in,
                              void* d_out, int out_size)
{
    const float* x_real = (const float*)d_in[0];
    const float* x_imag = (const float*)d_in[1];
    const float* W_real = (const float*)d_in[2];
    const float* W_imag = (const float*)d_in[3];

    const size_t nframes = (size_t)in_sizes[0] / NPT;   // 262144
    float* outR = (float*)d_out;
    float* outI = outR + nframes * NPT;                 // [real | imag]

    const int grid = (int)(nframes / FPB);              // 16384
    dft256_kernel<<<grid, BLOCK>>>(x_real, x_imag, W_real, W_imag, outR, outI);
}

// round 5
// speedup vs baseline: 1.3476x; 1.3476x over previous
#include <cuda_runtime.h>

// Batched 256-point complex DFT, out = FFT(x) / sqrt(256).
// Four-step: 256 = 16 x 16. 16 threads/frame, 16 frames per 256-thread block.
// Strided LDG.32/STG.32 (sector-coalesced; 32 loads front-batched for MLP).
// The 16x16 transpose goes through shared as packed float2, synced with
// __syncwarp (2 frames per warp). W16 twiddles are immediates. Step-2
// twiddles W256^{t*k}/16 are computed in registers via a power tree
// (no table, no LDS for twiddles, no block-wide barrier).
// NOTE: no min-blocks occupancy hint — R4 showed that squeezing registers
// destroys load batching (MLP) and costs far more than occupancy gains.

#define NPT      256
#define FPB      16
#define BLOCK    256
#define ROWS     17                 // padded row stride, float2 units
#define FS2      (16 * ROWS)        // frame stride, float2 units (272)

__device__ __forceinline__ float2 cmul(float2 a, float2 b)
{
    return make_float2(a.x * b.x - a.y * b.y,
                       a.x * b.y + a.y * b.x);
}

__device__ __forceinline__ void dft4(
    float& r0, float& i0, float& r1, float& i1,
    float& r2, float& i2, float& r3, float& i3)
{
    float t0r = r0 + r2, t0i = i0 + i2;
    float t1r = r0 - r2, t1i = i0 - i2;
    float t2r = r1 + r3, t2i = i1 + i3;
    float t3r = r1 - r3, t3i = i1 - i3;
    r0 = t0r + t2r;  i0 = t0i + t2i;
    r2 = t0r - t2r;  i2 = t0i - t2i;
    r1 = t1r + t3i;  i1 = t1i - t3r;   // t1 - i*t3
    r3 = t1r - t3i;  i3 = t1i + t3r;   // t1 + i*t3
}

// In-register forward 16-pt DFT (two radix-4 stages, DIT).
// Output X[4*k1+k2] lives in slot (4*k2+k1); callers remap with rev4().
__device__ __forceinline__ void fft16(float* xr, float* xi)
{
    constexpr float WR[10] = {
        1.f,  0.92387953251128674f,  0.70710678118654752f,  0.38268343236508977f,
        0.f, -0.38268343236508977f, -0.70710678118654752f, -0.92387953251128674f,
       -1.f, -0.92387953251128674f };
    constexpr float WI[10] = {
        0.f, -0.38268343236508977f, -0.70710678118654752f, -0.92387953251128674f,
       -1.f, -0.92387953251128674f, -0.70710678118654752f, -0.38268343236508977f,
        0.f,  0.38268343236508977f };

#pragma unroll
    for (int n1 = 0; n1 < 4; n1++) {
        dft4(xr[n1],    xi[n1],
             xr[n1+4],  xi[n1+4],
             xr[n1+8],  xi[n1+8],
             xr[n1+12], xi[n1+12]);
    }
#pragma unroll
    for (int n1 = 1; n1 < 4; n1++) {
#pragma unroll
        for (int k2 = 1; k2 < 4; k2++) {
            int s = n1 + 4 * k2;
            int m = n1 * k2;               // 1..9
            float wr = WR[m], wi = WI[m];
            float ar = xr[s], ai = xi[s];
            xr[s] = ar * wr - ai * wi;
            xi[s] = ar * wi + ai * wr;
        }
    }
#pragma unroll
    for (int k2 = 0; k2 < 4; k2++) {
        dft4(xr[4*k2+0], xi[4*k2+0],
             xr[4*k2+1], xi[4*k2+1],
             xr[4*k2+2], xi[4*k2+2],
             xr[4*k2+3], xi[4*k2+3]);
    }
}

__device__ __forceinline__ int rev4(int k) { return ((k & 3) << 2) | (k >> 2); }

__global__ void __launch_bounds__(BLOCK)
dft256_kernel(const float* __restrict__ xr, const float* __restrict__ xi,
              const float* __restrict__ Wr, const float* __restrict__ Wi,
              float* __restrict__ outR, float* __restrict__ outI)
{
    __shared__ float2 sh[FPB * FS2];     // transpose buffer (re,im packed)

    const int tid = threadIdx.x;
    const int f = tid >> 4;              // frame within block
    const int t = tid & 15;              // lane within frame (half-warp local)

    const size_t frame = (size_t)blockIdx.x * FPB + f;
    const float* xrp = xr + frame * NPT;
    const float* xip = xi + frame * NPT;

    // ---- step 1: strided coalesced loads (front-batched), first fft16 ----
    float ar[16], ai[16];
#pragma unroll
    for (int n2 = 0; n2 < 16; n2++) {
        ar[n2] = __ldcs(xrp + n2 * 16 + t);
        ai[n2] = __ldcs(xip + n2 * 16 + t);
    }
    fft16(ar, ai);

    // ---- step-2 twiddles in registers: W256^{t*k} / 16 via power tree ----
    // w1 = W256^t from row 1 of W; w^{4h+l} = Q[h] * L[l], Q pre-scaled.
    float2 w1 = make_float2(Wr[NPT + t], Wi[NPT + t]);
    float2 w2 = cmul(w1, w1);
    float2 w3 = cmul(w2, w1);
    float2 w4 = cmul(w2, w2);
    float2 w8 = cmul(w4, w4);
    float2 L[4] = { make_float2(1.f, 0.f), w1, w2, w3 };
    float2 Q[4];
    Q[0] = make_float2(0.0625f, 0.f);
    Q[1] = make_float2(0.0625f * w4.x, 0.0625f * w4.y);
    Q[2] = make_float2(0.0625f * w8.x, 0.0625f * w8.y);
    Q[3] = cmul(Q[2], w4);               // w12 / 16

    // ---- step 2: twiddle + transposed float2 STS ----
    float2* s = sh + f * FS2;
#pragma unroll
    for (int k = 0; k < 16; k++) {
        int sl = rev4(k);
        float2 wk = cmul(Q[k >> 2], L[k & 3]);
        float2 v  = make_float2(ar[sl], ai[sl]);
        s[k * ROWS + t] = cmul(v, wk);
    }
    __syncwarp();                        // transpose is intra-warp (2 frames/warp)

    // ---- step 3: row LDS.64, second fft16 (over n1) ----
    float br[16], bi[16];
#pragma unroll
    for (int n1 = 0; n1 < 16; n1++) {
        float2 v = s[t * ROWS + n1];
        br[n1] = v.x;  bi[n1] = v.y;
    }
    fft16(br, bi);

    // ---- step 4: strided coalesced streaming stores ----
    float* orp = outR + frame * NPT;
    float* oip = outI + frame * NPT;
#pragma unroll
    for (int k1 = 0; k1 < 16; k1++) {
        int sl = rev4(k1);
        __stcs(orp + k1 * 16 + t, br[sl]);
        __stcs(oip + k1 * 16 + t, bi[sl]);
    }
}

extern "C" void kernel_launch(void* const* d_in, const int* in_sizes, int n_in,
                              void* d_out, int out_size)
{
    const float* x_real = (const float*)d_in[0];
    const float* x_imag = (const float*)d_in[1];
    const float* W_real = (const float*)d_in[2];
    const float* W_imag = (const float*)d_in[3];

    const size_t nframes = (size_t)in_sizes[0] / NPT;   // 262144
    float* outR = (float*)d_out;
    float* outI = outR + nframes * NPT;                 // [real | imag]

    const int grid = (int)(nframes / FPB);              // 16384
    dft256_kernel<<<grid, BLOCK>>>(x_real, x_imag, W_real, W_imag, outR, outI);
}

// round 6
// speedup vs baseline: 1.3553x; 1.0057x over previous
#include <cuda_runtime.h>

// Batched 256-point complex DFT, out = FFT(x) / sqrt(256).
// Four-step: 256 = 16 x 16. 16 threads/frame, 4 frames per 64-thread block.
// Strided LDG.32/STG.32 (sector-coalesced; 32 loads front-batched for MLP).
// The 16x16 transpose goes through shared as packed float2, synced with
// __syncwarp (2 frames per warp). W16 twiddles are immediates. Step-2
// twiddles W256^{t*k}/16 are computed in registers via a power tree.
// There is NO block-wide barrier anywhere, so block size is pure packaging:
// 64-thread blocks give 21 CTAs/SM (vs 5 at 256) -> more resident warps to
// hide the front-batched load latency, identical per-thread codegen.

#define NPT      256
#define FPB      4
#define BLOCK    64
#define ROWS     17                 // padded row stride, float2 units
#define FS2      (16 * ROWS)        // frame stride, float2 units (272)

__device__ __forceinline__ float2 cmul(float2 a, float2 b)
{
    return make_float2(a.x * b.x - a.y * b.y,
                       a.x * b.y + a.y * b.x);
}

__device__ __forceinline__ void dft4(
    float& r0, float& i0, float& r1, float& i1,
    float& r2, float& i2, float& r3, float& i3)
{
    float t0r = r0 + r2, t0i = i0 + i2;
    float t1r = r0 - r2, t1i = i0 - i2;
    float t2r = r1 + r3, t2i = i1 + i3;
    float t3r = r1 - r3, t3i = i1 - i3;
    r0 = t0r + t2r;  i0 = t0i + t2i;
    r2 = t0r - t2r;  i2 = t0i - t2i;
    r1 = t1r + t3i;  i1 = t1i - t3r;   // t1 - i*t3
    r3 = t1r - t3i;  i3 = t1i + t3r;   // t1 + i*t3
}

// In-register forward 16-pt DFT (two radix-4 stages, DIT).
// Output X[4*k1+k2] lives in slot (4*k2+k1); callers remap with rev4().
__device__ __forceinline__ void fft16(float* xr, float* xi)
{
    constexpr float WR[10] = {
        1.f,  0.92387953251128674f,  0.70710678118654752f,  0.38268343236508977f,
        0.f, -0.38268343236508977f, -0.70710678118654752f, -0.92387953251128674f,
       -1.f, -0.92387953251128674f };
    constexpr float WI[10] = {
        0.f, -0.38268343236508977f, -0.70710678118654752f, -0.92387953251128674f,
       -1.f, -0.92387953251128674f, -0.70710678118654752f, -0.38268343236508977f,
        0.f,  0.38268343236508977f };

#pragma unroll
    for (int n1 = 0; n1 < 4; n1++) {
        dft4(xr[n1],    xi[n1],
             xr[n1+4],  xi[n1+4],
             xr[n1+8],  xi[n1+8],
             xr[n1+12], xi[n1+12]);
    }
#pragma unroll
    for (int n1 = 1; n1 < 4; n1++) {
#pragma unroll
        for (int k2 = 1; k2 < 4; k2++) {
            int s = n1 + 4 * k2;
            int m = n1 * k2;               // 1..9
            float wr = WR[m], wi = WI[m];
            float ar = xr[s], ai = xi[s];
            xr[s] = ar * wr - ai * wi;
            xi[s] = ar * wi + ai * wr;
        }
    }
#pragma unroll
    for (int k2 = 0; k2 < 4; k2++) {
        dft4(xr[4*k2+0], xi[4*k2+0],
             xr[4*k2+1], xi[4*k2+1],
             xr[4*k2+2], xi[4*k2+2],
             xr[4*k2+3], xi[4*k2+3]);
    }
}

__device__ __forceinline__ int rev4(int k) { return ((k & 3) << 2) | (k >> 2); }

__global__ void __launch_bounds__(BLOCK)
dft256_kernel(const float* __restrict__ xr, const float* __restrict__ xi,
              const float* __restrict__ Wr, const float* __restrict__ Wi,
              float* __restrict__ outR, float* __restrict__ outI)
{
    __shared__ float2 sh[FPB * FS2];     // transpose buffer (re,im packed)

    const int tid = threadIdx.x;
    const int f = tid >> 4;              // frame within block
    const int t = tid & 15;              // lane within frame (half-warp local)

    const size_t frame = (size_t)blockIdx.x * FPB + f;
    const float* xrp = xr + frame * NPT;
    const float* xip = xi + frame * NPT;

    // ---- step 1: strided coalesced loads (front-batched), first fft16 ----
    float ar[16], ai[16];
#pragma unroll
    for (int n2 = 0; n2 < 16; n2++) {
        ar[n2] = __ldcs(xrp + n2 * 16 + t);
        ai[n2] = __ldcs(xip + n2 * 16 + t);
    }
    fft16(ar, ai);

    // ---- step-2 twiddles in registers: W256^{t*k} / 16 via power tree ----
    // w1 = W256^t from row 1 of W; w^{4h+l} = Q[h] * L[l], Q pre-scaled.
    float2 w1 = make_float2(Wr[NPT + t], Wi[NPT + t]);
    float2 w2 = cmul(w1, w1);
    float2 w3 = cmul(w2, w1);
    float2 w4 = cmul(w2, w2);
    float2 w8 = cmul(w4, w4);
    float2 L[4] = { make_float2(1.f, 0.f), w1, w2, w3 };
    float2 Q[4];
    Q[0] = make_float2(0.0625f, 0.f);
    Q[1] = make_float2(0.0625f * w4.x, 0.0625f * w4.y);
    Q[2] = make_float2(0.0625f * w8.x, 0.0625f * w8.y);
    Q[3] = cmul(Q[2], w4);               // w12 / 16

    // ---- step 2: twiddle + transposed float2 STS ----
    float2* s = sh + f * FS2;
#pragma unroll
    for (int k = 0; k < 16; k++) {
        int sl = rev4(k);
        float2 wk = cmul(Q[k >> 2], L[k & 3]);
        float2 v  = make_float2(ar[sl], ai[sl]);
        s[k * ROWS + t] = cmul(v, wk);
    }
    __syncwarp();                        // transpose is intra-warp (2 frames/warp)

    // ---- step 3: row LDS.64, second fft16 (over n1) ----
    float br[16], bi[16];
#pragma unroll
    for (int n1 = 0; n1 < 16; n1++) {
        float2 v = s[t * ROWS + n1];
        br[n1] = v.x;  bi[n1] = v.y;
    }
    fft16(br, bi);

    // ---- step 4: strided coalesced streaming stores ----
    float* orp = outR + frame * NPT;
    float* oip = outI + frame * NPT;
#pragma unroll
    for (int k1 = 0; k1 < 16; k1++) {
        int sl = rev4(k1);
        __stcs(orp + k1 * 16 + t, br[sl]);
        __stcs(oip + k1 * 16 + t, bi[sl]);
    }
}

extern "C" void kernel_launch(void* const* d_in, const int* in_sizes, int n_in,
                              void* d_out, int out_size)
{
    const float* x_real = (const float*)d_in[0];
    const float* x_imag = (const float*)d_in[1];
    const float* W_real = (const float*)d_in[2];
    const float* W_imag = (const float*)d_in[3];

    const size_t nframes = (size_t)in_sizes[0] / NPT;   // 262144
    float* outR = (float*)d_out;
    float* outI = outR + nframes * NPT;                 // [real | imag]

    const int grid = (int)(nframes / FPB);              // 65536
    dft256_kernel<<<grid, BLOCK>>>(x_real, x_imag, W_real, W_imag, outR, outI);
}

// round 7
// speedup vs baseline: 1.3681x; 1.0095x over previous
#include <cuda_runtime.h>

// Batched 256-point complex DFT, out = FFT(x) / sqrt(256).
// Four-step: 256 = 16 x 16. 16 threads/frame, 4 frames per 64-thread block,
// and TWO frame-groups per block with register double-buffering:
// both groups' 64 strided loads are front-batched, so while group 0 runs
// its FFT/transpose/stores, group 1's loads are in flight -> each warp keeps
// deep outstanding-load pressure on DRAM at all times (R6 showed extra
// warps alone can't close the DRAM gaps; per-warp MLP can).
// W16 twiddles are immediates; W256^{t*k}/16 via register power tree,
// computed ONCE and reused for both groups. No block-wide barriers.

#define NPT      256
#define FPB      4
#define BLOCK    64
#define GRPS     2                  // frame-groups per block
#define ROWS     17                 // padded row stride, float2 units
#define FS2      (16 * ROWS)        // frame stride, float2 units (272)

__device__ __forceinline__ float2 cmul(float2 a, float2 b)
{
    return make_float2(a.x * b.x - a.y * b.y,
                       a.x * b.y + a.y * b.x);
}

__device__ __forceinline__ void dft4(
    float& r0, float& i0, float& r1, float& i1,
    float& r2, float& i2, float& r3, float& i3)
{
    float t0r = r0 + r2, t0i = i0 + i2;
    float t1r = r0 - r2, t1i = i0 - i2;
    float t2r = r1 + r3, t2i = i1 + i3;
    float t3r = r1 - r3, t3i = i1 - i3;
    r0 = t0r + t2r;  i0 = t0i + t2i;
    r2 = t0r - t2r;  i2 = t0i - t2i;
    r1 = t1r + t3i;  i1 = t1i - t3r;   // t1 - i*t3
    r3 = t1r - t3i;  i3 = t1i + t3r;   // t1 + i*t3
}

// In-register forward 16-pt DFT (two radix-4 stages, DIT).
// Output X[4*k1+k2] lives in slot (4*k2+k1); callers remap with rev4().
__device__ __forceinline__ void fft16(float* xr, float* xi)
{
    constexpr float WR[10] = {
        1.f,  0.92387953251128674f,  0.70710678118654752f,  0.38268343236508977f,
        0.f, -0.38268343236508977f, -0.70710678118654752f, -0.92387953251128674f,
       -1.f, -0.92387953251128674f };
    constexpr float WI[10] = {
        0.f, -0.38268343236508977f, -0.70710678118654752f, -0.92387953251128674f,
       -1.f, -0.92387953251128674f, -0.70710678118654752f, -0.38268343236508977f,
        0.f,  0.38268343236508977f };

#pragma unroll
    for (int n1 = 0; n1 < 4; n1++) {
        dft4(xr[n1],    xi[n1],
             xr[n1+4],  xi[n1+4],
             xr[n1+8],  xi[n1+8],
             xr[n1+12], xi[n1+12]);
    }
#pragma unroll
    for (int n1 = 1; n1 < 4; n1++) {
#pragma unroll
        for (int k2 = 1; k2 < 4; k2++) {
            int s = n1 + 4 * k2;
            int m = n1 * k2;               // 1..9
            float wr = WR[m], wi = WI[m];
            float ar = xr[s], ai = xi[s];
            xr[s] = ar * wr - ai * wi;
            xi[s] = ar * wi + ai * wr;
        }
    }
#pragma unroll
    for (int k2 = 0; k2 < 4; k2++) {
        dft4(xr[4*k2+0], xi[4*k2+0],
             xr[4*k2+1], xi[4*k2+1],
             xr[4*k2+2], xi[4*k2+2],
             xr[4*k2+3], xi[4*k2+3]);
    }
}

__device__ __forceinline__ int rev4(int k) { return ((k & 3) << 2) | (k >> 2); }

// FFT + twiddle + transpose + second FFT + stores for one frame.
// ar/ai are the 16 loaded values (consumed). s = this frame's shared slice.
__device__ __forceinline__ void process_frame(
    float* ar, float* ai, float2* s, int t,
    const float2* Q, const float2* L,
    float* __restrict__ orp, float* __restrict__ oip)
{
    fft16(ar, ai);

#pragma unroll
    for (int k = 0; k < 16; k++) {
        int sl = rev4(k);
        float2 wk = cmul(Q[k >> 2], L[k & 3]);
        float2 v  = make_float2(ar[sl], ai[sl]);
        s[k * ROWS + t] = cmul(v, wk);
    }
    __syncwarp();                        // transpose is intra-warp

    float br[16], bi[16];
#pragma unroll
    for (int n1 = 0; n1 < 16; n1++) {
        float2 v = s[t * ROWS + n1];
        br[n1] = v.x;  bi[n1] = v.y;
    }
    __syncwarp();                        // WAR guard: buffer reused by next group
    fft16(br, bi);

#pragma unroll
    for (int k1 = 0; k1 < 16; k1++) {
        int sl = rev4(k1);
        __stcs(orp + k1 * 16 + t, br[sl]);
        __stcs(oip + k1 * 16 + t, bi[sl]);
    }
}

__global__ void __launch_bounds__(BLOCK)
dft256_kernel(const float* __restrict__ xr, const float* __restrict__ xi,
              const float* __restrict__ Wr, const float* __restrict__ Wi,
              float* __restrict__ outR, float* __restrict__ outI)
{
    __shared__ float2 sh[FPB * FS2];     // transpose buffer (reused per group)

    const int tid = threadIdx.x;
    const int f = tid >> 4;              // frame within group
    const int t = tid & 15;              // lane within frame (half-warp local)

    const size_t frame0 = ((size_t)blockIdx.x * GRPS) * FPB + f;       // group 0
    const size_t frame1 = frame0 + FPB;                                 // group 1
    const float* xr0 = xr + frame0 * NPT;
    const float* xi0 = xi + frame0 * NPT;
    const float* xr1 = xr + frame1 * NPT;
    const float* xi1 = xi + frame1 * NPT;

    // ---- front-batch BOTH groups' loads (deep per-warp MLP) ----
    float ar[16], ai[16], cr[16], ci[16];
#pragma unroll
    for (int n2 = 0; n2 < 16; n2++) {
        ar[n2] = __ldcs(xr0 + n2 * 16 + t);
        ai[n2] = __ldcs(xi0 + n2 * 16 + t);
    }
#pragma unroll
    for (int n2 = 0; n2 < 16; n2++) {
        cr[n2] = __ldcs(xr1 + n2 * 16 + t);
        ci[n2] = __ldcs(xi1 + n2 * 16 + t);
    }

    // ---- step-2 twiddles in registers (shared by both groups) ----
    float2 w1 = make_float2(Wr[NPT + t], Wi[NPT + t]);   // W256^t
    float2 w2 = cmul(w1, w1);
    float2 w3 = cmul(w2, w1);
    float2 w4 = cmul(w2, w2);
    float2 w8 = cmul(w4, w4);
    float2 L[4] = { make_float2(1.f, 0.f), w1, w2, w3 };
    float2 Q[4];
    Q[0] = make_float2(0.0625f, 0.f);
    Q[1] = make_float2(0.0625f * w4.x, 0.0625f * w4.y);
    Q[2] = make_float2(0.0625f * w8.x, 0.0625f * w8.y);
    Q[3] = cmul(Q[2], w4);               // w12 / 16

    float2* s = sh + f * FS2;

    // ---- group 0: compute + store while group 1 loads are in flight ----
    process_frame(ar, ai, s, t, Q, L,
                  outR + frame0 * NPT, outI + frame0 * NPT);

    // ---- group 1 ----
    process_frame(cr, ci, s, t, Q, L,
                  outR + frame1 * NPT, outI + frame1 * NPT);
}

extern "C" void kernel_launch(void* const* d_in, const int* in_sizes, int n_in,
                              void* d_out, int out_size)
{
    const float* x_real = (const float*)d_in[0];
    const float* x_imag = (const float*)d_in[1];
    const float* W_real = (const float*)d_in[2];
    const float* W_imag = (const float*)d_in[3];

    const size_t nframes = (size_t)in_sizes[0] / NPT;   // 262144
    float* outR = (float*)d_out;
    float* outI = outR + nframes * NPT;                 // [real | imag]

    const int grid = (int)(nframes / (FPB * GRPS));     // 32768
    dft256_kernel<<<grid, BLOCK>>>(x_real, x_imag, W_real, W_imag, outR, outI);
}